// round 14
// baseline (speedup 1.0000x reference)
#include <cuda_runtime.h>
#include <cuda_fp16.h>
#include <cstdint>
#include <math.h>

#define TOTP 500000
#define BATCH 64
#define KTOT 398
#define CLIP0 1.0f
#define CLIP1 1.0f

__device__ float g_E[BATCH * KTOT];
__device__ float g_rsq[BATCH];
__device__ __align__(16) __half g_residH[(size_t)BATCH * TOTP];   // 64MB
// fp16 Bm copies, rows padded to 16B multiples: 104 | 160 | 144 halves per row
#define BMH_OFF1 10400000
#define BMH_OFF2 46400000
__device__ __align__(16) __half g_BmH[71600000];                  // 143MB

// ---------------- helpers ----------------
__device__ __forceinline__ uint32_t smem_u32(const void* p) {
    uint32_t a;
    asm("{ .reg .u64 t; cvta.to.shared.u64 t, %1; cvt.u32.u64 %0, t; }" : "=r"(a) : "l"(p));
    return a;
}
__device__ __forceinline__ uint32_t cvt_h16(float x, float y) {
    __half2 h = __floats2half2_rn(x, y);
    return *(uint32_t*)&h;
}
#define LDSM_X4(r, a) \
    asm volatile("ldmatrix.sync.aligned.m8n8.x4.shared.b16 {%0,%1,%2,%3}, [%4];" \
        : "=r"((r)[0]), "=r"((r)[1]), "=r"((r)[2]), "=r"((r)[3]) : "r"(a))
#define LDSM_X4T(r, a) \
    asm volatile("ldmatrix.sync.aligned.m8n8.x4.trans.shared.b16 {%0,%1,%2,%3}, [%4];" \
        : "=r"((r)[0]), "=r"((r)[1]), "=r"((r)[2]), "=r"((r)[3]) : "r"(a))
#define MMA16816(d, a, b0, b1) \
    asm volatile("mma.sync.aligned.m16n8k16.row.col.f32.f16.f16.f32 " \
        "{%0,%1,%2,%3}, {%4,%5,%6,%7}, {%8,%9}, {%0,%1,%2,%3};" \
        : "+f"((d)[0]), "+f"((d)[1]), "+f"((d)[2]), "+f"((d)[3]) \
        : "r"((a)[0]), "r"((a)[1]), "r"((a)[2]), "r"((a)[3]), "r"(b0), "r"(b1))

__device__ __forceinline__ void cp_async16(uint32_t d, const void* s, int bytes) {
    asm volatile("cp.async.cg.shared.global [%0], [%1], 16, %2;" :: "r"(d), "l"(s), "r"(bytes));
}
__device__ __forceinline__ void cp_commit()  { asm volatile("cp.async.commit_group;" ::: "memory"); }
template <int N>
__device__ __forceinline__ void cp_waitg()   { asm volatile("cp.async.wait_group %0;" :: "n"(N) : "memory"); }

// ---------------- small kernels ----------------
__global__ void k_init(float* __restrict__ out_tg) {
    const int i = blockIdx.x * blockDim.x + threadIdx.x;
    const int stride = gridDim.x * blockDim.x;
    for (int t = i; t < TOTP; t += stride) out_tg[t] = 0.0f;
    if (i < BATCH * KTOT) g_E[i] = 0.0f;
    if (i < BATCH) g_rsq[i] = 0.0f;
}

__global__ void k_embed(float* __restrict__ out) {
    __shared__ float scale[BATCH];
    const int tid = threadIdx.x;
    if (tid < BATCH) {
        float s = 0.0f;
        for (int j = 0; j < KTOT; j++) { float v = g_E[tid * KTOT + j]; s += v * v; }
        float n = sqrtf(s);
        scale[tid] = ((n > CLIP0) ? (CLIP0 / n) : 1.0f) * (1.0f / BATCH);
    }
    __syncthreads();
    for (int j = tid; j < KTOT; j += blockDim.x) {
        float s = 0.0f;
        for (int b = 0; b < BATCH; b++) s += g_E[b * KTOT + j] * scale[b];
        out[j] = s;
    }
}

__global__ __launch_bounds__(256) void k_final(float* __restrict__ out_resid) {
    __shared__ float scale[BATCH];
    const int tid = threadIdx.x;
    if (tid < BATCH) {
        float n = sqrtf(g_rsq[tid]);
        scale[tid] = ((n > CLIP1) ? (CLIP1 / n) : 1.0f) * (1.0f / BATCH);
    }
    __syncthreads();
    const int p8 = blockIdx.x * blockDim.x + tid;
    if (p8 < TOTP / 8) {
        float s[8];
#pragma unroll
        for (int j = 0; j < 8; j++) s[j] = 0.0f;
        const size_t base = (size_t)p8 * 8;
#pragma unroll 4
        for (int b = 0; b < BATCH; b++) {
            uint4 v = *(const uint4*)(g_residH + (size_t)b * TOTP + base);
            const float sc = scale[b];
            const uint32_t* w = (const uint32_t*)&v;
#pragma unroll
            for (int q = 0; q < 4; q++) {
                float2 f = __half22float2(*(const __half2*)&w[q]);
                s[2 * q] += f.x * sc; s[2 * q + 1] += f.y * sc;
            }
        }
#pragma unroll
        for (int q = 0; q < 4; q++)
            *(float2*)&out_resid[base + 2 * q] = make_float2(s[2 * q], s[2 * q + 1]);
    }
}

// =============== GEMM1 (single-fp16 HMMA, double-buffered) + fp16 Bm export ===============
template <int KG, int NPAD, int KGP2>
__device__ void gemm1_body(const float* __restrict__ G, const float* __restrict__ Bm,
                           __half* __restrict__ BmH, int numP, int pbase, int koff,
                           int chunk, int bid)
{
    constexpr int NH = NPAD / 2, NT = NH / 8, NG = NT / 2;
    constexpr int SBH = NPAD + 8;
    constexpr int GSTR = 20;
    constexpr int BN = NPAD / 16;
    constexpr int GBUF = 64 * GSTR * 4;      // 5120
    constexpr int OFF_B = 2 * GBUF;          // 10240
    constexpr int BBUF = 32 * SBH * 2;

    extern __shared__ char smem[];
    const uint32_t sb32 = smem_u32(smem);
    const int tid = threadIdx.x, wid = tid >> 5, lane = tid & 31;
    const int wr = wid >> 1, wc = wid & 1;

    const int pstart = bid * chunk;
    const int pend = min(pstart + chunk, numP);
    if (pstart >= numP) return;
    const int nsteps = (pend - pstart + 31) >> 5;

    float2 gpre[4];
    float2 bpre[BN];

    auto ldg_step = [&](int pt) {
#pragma unroll
        for (int j = 0; j < 4; j++) {
            int idx = tid + j * 256;
            int b = idx >> 4, pp = idx & 15, p = pt + 2 * pp;
            gpre[j] = (p < pend) ? *(const float2*)&G[(size_t)b * TOTP + pbase + p]
                                 : make_float2(0.f, 0.f);
        }
#pragma unroll
        for (int j = 0; j < BN; j++) {
            int idx = tid + j * 256;
            int k = idx / NH, h = idx % NH, c = 2 * h, p = pt + k;
            bpre[j] = (p < pend && c < KG) ? *(const float2*)&Bm[(size_t)p * KG + c]
                                           : make_float2(0.f, 0.f);
        }
    };
    auto sts_step = [&](int buf, int pt) {
        char* gb = smem + buf * GBUF;
        char* bb = smem + OFF_B + buf * BBUF;
#pragma unroll
        for (int j = 0; j < 4; j++) {
            int idx = tid + j * 256;
            int b = idx >> 4, pp = idx & 15;
            ((uint32_t*)gb)[b * GSTR + pp] = cvt_h16(gpre[j].x, gpre[j].y);
        }
#pragma unroll
        for (int j = 0; j < BN; j++) {
            int idx = tid + j * 256;
            int k = idx / NH, h = idx % NH;
            uint32_t v16 = cvt_h16(bpre[j].x, bpre[j].y);
            ((uint32_t*)bb)[k * (SBH / 2) + h] = v16;
            int p = pt + k;
            if (p < pend && 2 * h < KGP2)
                *(uint32_t*)(BmH + (size_t)p * KGP2 + 2 * h) = v16;
        }
    };

    float acc[NT][4];
#pragma unroll
    for (int t = 0; t < NT; t++)
#pragma unroll
        for (int i = 0; i < 4; i++) acc[t][i] = 0.0f;

    ldg_step(pstart);
    sts_step(0, pstart);
    __syncthreads();

    for (int s = 0; s < nsteps; s++) {
        const int cur = s & 1;
        if (s + 1 < nsteps) ldg_step(pstart + (s + 1) * 32);
        const uint32_t gB = sb32 + cur * GBUF;
        const uint32_t bB = sb32 + OFF_B + cur * BBUF;
#pragma unroll
        for (int kk = 0; kk < 2; kk++) {
            uint32_t ah[4];
            uint32_t ra = (uint32_t)((wr * 16 + (lane & 15)) * 80 + kk * 32 + (lane >> 4) * 16);
            LDSM_X4(ah, gB + ra);
            uint32_t rb = (uint32_t)((kk * 16 + (lane & 15)) * (SBH * 2));
#pragma unroll
            for (int g = 0; g < NG; g++) {
                uint32_t cb = (uint32_t)((wc * NH + g * 16 + (lane >> 4) * 8) * 2);
                uint32_t bh[4];
                LDSM_X4T(bh, bB + rb + cb);
                MMA16816(acc[2 * g],     ah, bh[0], bh[1]);
                MMA16816(acc[2 * g + 1], ah, bh[2], bh[3]);
            }
        }
        if (s + 1 < nsteps) sts_step(cur ^ 1, pstart + (s + 1) * 32);
        __syncthreads();
    }

    const int m0 = wr * 16 + (lane >> 2);
#pragma unroll
    for (int t = 0; t < NT; t++) {
        int n0 = wc * NH + t * 8 + (lane & 3) * 2;
        if (n0 < KG) {
            atomicAdd(&g_E[m0 * KTOT + koff + n0], acc[t][0]);
            atomicAdd(&g_E[(m0 + 8) * KTOT + koff + n0], acc[t][2]);
        }
        if (n0 + 1 < KG) {
            atomicAdd(&g_E[m0 * KTOT + koff + n0 + 1], acc[t][1]);
            atomicAdd(&g_E[(m0 + 8) * KTOT + koff + n0 + 1], acc[t][3]);
        }
    }
}

__global__ __launch_bounds__(256, 2) void k_gemm1_all(
    const float* __restrict__ G, const float* __restrict__ B0,
    const float* __restrict__ B1, const float* __restrict__ B2)
{
    const int bx = blockIdx.x;
    if (bx < 48)       gemm1_body<104,128,104>(G, B0, g_BmH,            100000,      0,   0, 2112, bx);
    else if (bx < 194) gemm1_body<156,160,160>(G, B1, g_BmH + BMH_OFF1, 225000, 100000, 104, 1568, bx - 48);
    else               gemm1_body<138,160,144>(G, B2, g_BmH + BMH_OFF2, 175000, 325000, 260, 1728, bx - 194);
}

// =============== GEMM2 (transposed): D[b][p] = sum_k E[b][k]*Bm[p][k] =====================
// A = E (register fragments, loaded once); B = Bm fp16, TILE-granular cp.async ring:
// 3 tile-buffers x KK slots, ONE commit / ONE wait / ONE sync per tile.
template <int KG, int KK, int KGP2>
__device__ void gemm2_body(const float* __restrict__ G, const __half* __restrict__ BmH,
                           float* __restrict__ out_tg, int numP, int pbase, int koff,
                           int ntiles, int cl, int NCg)
{
    constexpr int KPAD = KK * 32;
    constexpr int NK16 = 2 * KK;
    constexpr int SBH = KPAD + 8;
    constexpr int ESZ = 64 * SBH * 2;
    constexpr int OFF_RING = ESZ;
    constexpr int SSZ = 64 * 80;             // 64 rows x 80B per k32 slot

    extern __shared__ char smem[];
    const uint32_t sb32 = smem_u32(smem);
    const int tid = threadIdx.x, wid = tid >> 5, lane = tid & 31;
    const int wr = wid >> 1, wc = wid & 1;

    // stage E (single fp16)
    for (int idx = tid; idx < 64 * (KPAD / 2); idx += 256) {
        int b = idx / (KPAD / 2), h = idx % (KPAD / 2), k = 2 * h;
        float2 v = make_float2(0.f, 0.f);
        if (k < KG) v = *(const float2*)&g_E[b * KTOT + koff + k];
        ((uint32_t*)smem)[b * (SBH / 2) + h] = cvt_h16(v.x, v.y);
    }
    __syncthreads();

    // load E fragments once
    uint32_t ef[NK16][4];
#pragma unroll
    for (int j = 0; j < NK16; j++) {
        uint32_t ra = (uint32_t)((wr * 16 + (lane & 15)) * (SBH * 2) + j * 32 + (lane >> 4) * 16);
        LDSM_X4(ef[j], sb32 + ra);
    }

    const int myT = (cl < ntiles) ? ((ntiles - cl + NCg - 1) / NCg) : 0;

    const int r_cp = tid >> 2, ch_cp = tid & 3;
    // issue a WHOLE tile (KK chunk loads per thread), caller commits once
    auto issue_tile = [&](int tj, int buf) {
        if (tj >= myT) return;
        const int p0 = (cl + tj * NCg) * 64;
        const int p = p0 + r_cp;
        const uint32_t dbase = sb32 + OFF_RING + buf * (KK * SSZ) + r_cp * 80 + ch_cp * 16;
#pragma unroll
        for (int st = 0; st < KK; st++) {
            const int kb = st * 64 + ch_cp * 16;
            int rem = (p < numP) ? (KG * 2 - kb) : 0;
            int bytes = rem <= 0 ? 0 : (rem >= 16 ? 16 : rem);
            const char* src = (const char*)BmH + (bytes > 0 ? ((size_t)p * KGP2 * 2 + kb) : 0);
            cp_async16(dbase + st * SSZ, src, bytes);
        }
    };

    const int bA = wr * 16 + (lane >> 2), bB = bA + 8;
    const int pofs = wc * 32 + (lane & 3) * 2;
    float gpre[16];
    float acc[4][4];
    float rsA = 0.f, rsB = 0.f;
#pragma unroll
    for (int t = 0; t < 4; t++)
#pragma unroll
        for (int i = 0; i < 4; i++) acc[t][i] = 0.0f;

    issue_tile(0, 0); cp_commit();
    issue_tile(1, 1); cp_commit();

    for (int tj = 0; tj < myT; tj++) {
        const int tile = cl + tj * NCg;
        const int p0 = tile * 64;
        cp_waitg<1>();
        __syncthreads();

        // prefetch G for this tile's epilogue (overlaps MMA)
#pragma unroll
        for (int t = 0; t < 4; t++) {
            int p = p0 + pofs + t * 8;
            bool v = p < numP;
            float2 a = v ? *(const float2*)&G[(size_t)bA * TOTP + pbase + p] : make_float2(0.f, 0.f);
            float2 b = v ? *(const float2*)&G[(size_t)bB * TOTP + pbase + p] : make_float2(0.f, 0.f);
            gpre[4 * t + 0] = a.x; gpre[4 * t + 1] = a.y;
            gpre[4 * t + 2] = b.x; gpre[4 * t + 3] = b.y;
        }

        const uint32_t bufB = sb32 + OFF_RING + (tj % 3) * (KK * SSZ);
#pragma unroll
        for (int st = 0; st < KK; st++) {
            const uint32_t aB = bufB + st * SSZ;
#pragma unroll
            for (int kk2 = 0; kk2 < 2; kk2++) {
                const int j = st * 2 + kk2;
#pragma unroll
                for (int g = 0; g < 2; g++) {
                    uint32_t rb = (uint32_t)((wc * 32 + g * 16 + (lane & 15)) * 80 + kk2 * 32 + (lane >> 4) * 16);
                    uint32_t bh[4];
                    LDSM_X4(bh, aB + rb);
                    MMA16816(acc[2 * g],     ef[j], bh[0], bh[2]);
                    MMA16816(acc[2 * g + 1], ef[j], bh[1], bh[3]);
                }
            }
        }

        issue_tile(tj + 2, (tj + 2) % 3); cp_commit();

        // epilogue: residual (fp16), rsq, colsum->out_tg atomics
        float cs[8];
#pragma unroll
        for (int t = 0; t < 4; t++) {
            const int p = p0 + pofs + t * 8;
            const bool v = p < numP;
            const size_t gp = (size_t)(pbase + p);
            float gA0 = gpre[4 * t + 0], gA1 = gpre[4 * t + 1];
            float gB0 = gpre[4 * t + 2], gB1 = gpre[4 * t + 3];
            float rA0 = gA0 - acc[t][0], rA1 = gA1 - acc[t][1];
            float rB0 = gB0 - acc[t][2], rB1 = gB1 - acc[t][3];
            if (v) {
                __half2 hA = __floats2half2_rn(rA0, rA1);
                __half2 hB = __floats2half2_rn(rB0, rB1);
                *(uint32_t*)(g_residH + (size_t)bA * TOTP + gp) = *(uint32_t*)&hA;
                *(uint32_t*)(g_residH + (size_t)bB * TOTP + gp) = *(uint32_t*)&hB;
            }
            rsA += rA0 * rA0 + rA1 * rA1;
            rsB += rB0 * rB0 + rB1 * rB1;
            cs[2 * t]     = gA0 + gB0;
            cs[2 * t + 1] = gA1 + gB1;
#pragma unroll
            for (int i = 0; i < 4; i++) acc[t][i] = 0.0f;
        }
#pragma unroll
        for (int q = 0; q < 8; q++) {
            float v = cs[q];
            v += __shfl_xor_sync(~0u, v, 4);
            v += __shfl_xor_sync(~0u, v, 8);
            v += __shfl_xor_sync(~0u, v, 16);
            cs[q] = v;
        }
        if (lane < 4) {
#pragma unroll
            for (int t = 0; t < 4; t++) {
                int p = p0 + wc * 32 + t * 8 + lane * 2;
                if (p < numP)     atomicAdd(&out_tg[p],     cs[2 * t]     * (1.0f / BATCH));
                if (p + 1 < numP) atomicAdd(&out_tg[p + 1], cs[2 * t + 1] * (1.0f / BATCH));
            }
        }
    }
    cp_waitg<0>();

    rsA += __shfl_xor_sync(~0u, rsA, 1); rsA += __shfl_xor_sync(~0u, rsA, 2);
    rsB += __shfl_xor_sync(~0u, rsB, 1); rsB += __shfl_xor_sync(~0u, rsB, 2);
    if ((lane & 3) == 0) {
        atomicAdd(&g_rsq[bA], rsA);
        atomicAdd(&g_rsq[bB], rsB);
    }
}

__global__ __launch_bounds__(256, 2) void k_gemm2_all(
    const float* __restrict__ G, float* __restrict__ out_tg)
{
    const int bx = blockIdx.x;
    if (bx < 52)       gemm2_body<104,4,104>(G, g_BmH,            out_tg,          100000,      0,   0, 1563, bx,        52);
    else if (bx < 189) gemm2_body<156,5,160>(G, g_BmH + BMH_OFF1, out_tg + 100000, 225000, 100000, 104, 3516, bx - 52,  137);
    else               gemm2_body<138,5,144>(G, g_BmH + BMH_OFF2, out_tg + 325000, 175000, 325000, 260, 2735, bx - 189, 107);
}

// ---------------- launch ----------------
extern "C" void kernel_launch(void* const* d_in, const int* in_sizes, int n_in,
                              void* d_out, int out_size) {
    (void)in_sizes; (void)n_in; (void)out_size;
    const float* G  = (const float*)d_in[0];
    const float* B0 = (const float*)d_in[1];
    const float* B1 = (const float*)d_in[2];
    const float* B2 = (const float*)d_in[3];
    float* out = (float*)d_out;
    float* out_tg = out + 398 + TOTP;

    static bool attr_done = false;
    if (!attr_done) {
        cudaFuncSetAttribute(k_gemm2_all, cudaFuncAttributeMaxDynamicSharedMemorySize, 98304);
        attr_done = true;
    }

    k_init<<<256, 256>>>(out_tg);

    // gemm1: persistent, one wave (48+146+102 = 296 CTAs), byte-balanced
    k_gemm1_all<<<296, 256, 31744>>>(G, B0, B1, B2);

    k_embed<<<1, 256>>>(out);

    // gemm2 smem: ESZ(max 21504) + 3*5*5120 = 98304 (2 CTAs/SM: 196.6KB <= 228KB)
    k_gemm2_all<<<296, 256, 98304>>>(G, out_tg);

    k_final<<<(TOTP / 8 + 255) / 256, 256>>>(out + 398);
}

// round 15
// speedup vs baseline: 1.0188x; 1.0188x over previous
#include <cuda_runtime.h>
#include <cuda_fp16.h>
#include <cstdint>
#include <math.h>

#define TOTP 500000
#define BATCH 64
#define KTOT 398
#define CLIP0 1.0f
#define CLIP1 1.0f

__device__ float g_E[BATCH * KTOT];
__device__ float g_rsq[BATCH];
__device__ __align__(16) __half g_residH[(size_t)BATCH * TOTP];   // 64MB
// fp16 Bm copies, rows padded to 16B multiples: 104 | 160 | 144 halves per row
#define BMH_OFF1 10400000
#define BMH_OFF2 46400000
__device__ __align__(16) __half g_BmH[71600000];                  // 143MB

// ---------------- helpers ----------------
__device__ __forceinline__ uint32_t smem_u32(const void* p) {
    uint32_t a;
    asm("{ .reg .u64 t; cvta.to.shared.u64 t, %1; cvt.u32.u64 %0, t; }" : "=r"(a) : "l"(p));
    return a;
}
__device__ __forceinline__ uint32_t cvt_h16(float x, float y) {
    __half2 h = __floats2half2_rn(x, y);
    return *(uint32_t*)&h;
}
#define LDSM_X4(r, a) \
    asm volatile("ldmatrix.sync.aligned.m8n8.x4.shared.b16 {%0,%1,%2,%3}, [%4];" \
        : "=r"((r)[0]), "=r"((r)[1]), "=r"((r)[2]), "=r"((r)[3]) : "r"(a))
#define LDSM_X4T(r, a) \
    asm volatile("ldmatrix.sync.aligned.m8n8.x4.trans.shared.b16 {%0,%1,%2,%3}, [%4];" \
        : "=r"((r)[0]), "=r"((r)[1]), "=r"((r)[2]), "=r"((r)[3]) : "r"(a))
#define MMA16816(d, a, b0, b1) \
    asm volatile("mma.sync.aligned.m16n8k16.row.col.f32.f16.f16.f32 " \
        "{%0,%1,%2,%3}, {%4,%5,%6,%7}, {%8,%9}, {%0,%1,%2,%3};" \
        : "+f"((d)[0]), "+f"((d)[1]), "+f"((d)[2]), "+f"((d)[3]) \
        : "r"((a)[0]), "r"((a)[1]), "r"((a)[2]), "r"((a)[3]), "r"(b0), "r"(b1))

__device__ __forceinline__ void cp_async16(uint32_t d, const void* s, int bytes) {
    asm volatile("cp.async.cg.shared.global [%0], [%1], 16, %2;" :: "r"(d), "l"(s), "r"(bytes));
}
__device__ __forceinline__ void cp_commit()  { asm volatile("cp.async.commit_group;" ::: "memory"); }
template <int N>
__device__ __forceinline__ void cp_waitg()   { asm volatile("cp.async.wait_group %0;" :: "n"(N) : "memory"); }

// ---------------- small kernels ----------------
__global__ void k_init(float* __restrict__ out_tg) {
    const int i = blockIdx.x * blockDim.x + threadIdx.x;
    const int stride = gridDim.x * blockDim.x;
    for (int t = i; t < TOTP; t += stride) out_tg[t] = 0.0f;
    if (i < BATCH * KTOT) g_E[i] = 0.0f;
    if (i < BATCH) g_rsq[i] = 0.0f;
}

__global__ void k_embed(float* __restrict__ out) {
    __shared__ float scale[BATCH];
    const int tid = threadIdx.x;
    if (tid < BATCH) {
        float s = 0.0f;
        for (int j = 0; j < KTOT; j++) { float v = g_E[tid * KTOT + j]; s += v * v; }
        float n = sqrtf(s);
        scale[tid] = ((n > CLIP0) ? (CLIP0 / n) : 1.0f) * (1.0f / BATCH);
    }
    __syncthreads();
    for (int j = tid; j < KTOT; j += blockDim.x) {
        float s = 0.0f;
        for (int b = 0; b < BATCH; b++) s += g_E[b * KTOT + j] * scale[b];
        out[j] = s;
    }
}

__global__ __launch_bounds__(256) void k_final(float* __restrict__ out_resid) {
    __shared__ float scale[BATCH];
    const int tid = threadIdx.x;
    if (tid < BATCH) {
        float n = sqrtf(g_rsq[tid]);
        scale[tid] = ((n > CLIP1) ? (CLIP1 / n) : 1.0f) * (1.0f / BATCH);
    }
    __syncthreads();
    const int p8 = blockIdx.x * blockDim.x + tid;
    if (p8 < TOTP / 8) {
        float s[8];
#pragma unroll
        for (int j = 0; j < 8; j++) s[j] = 0.0f;
        const size_t base = (size_t)p8 * 8;
#pragma unroll 4
        for (int b = 0; b < BATCH; b++) {
            uint4 v = *(const uint4*)(g_residH + (size_t)b * TOTP + base);
            const float sc = scale[b];
            const uint32_t* w = (const uint32_t*)&v;
#pragma unroll
            for (int q = 0; q < 4; q++) {
                float2 f = __half22float2(*(const __half2*)&w[q]);
                s[2 * q] += f.x * sc; s[2 * q + 1] += f.y * sc;
            }
        }
#pragma unroll
        for (int q = 0; q < 4; q++)
            *(float2*)&out_resid[base + 2 * q] = make_float2(s[2 * q], s[2 * q + 1]);
    }
}

// =============== GEMM1 (single-fp16 HMMA, double-buffered, 128-bit staging) ===============
// E[b][c] += sum_p G[b][p]*Bm[p][c]; exports fp16 Bm. V4: Bm vectorized (KG%4==0).
template <int KG, int NPAD, int KGP2, bool V4>
__device__ void gemm1_body(const float* __restrict__ G, const float* __restrict__ Bm,
                           __half* __restrict__ BmH, int numP, int pbase, int koff,
                           int chunk, int bid)
{
    constexpr int NH = NPAD / 2, NT = NH / 8, NG = NT / 2;
    constexpr int SBH = NPAD + 8;
    constexpr int GSTR = 20;                 // u32 per G row (80B, ldmatrix conflict-free)
    constexpr int BN4 = NPAD / 32;           // float4/thread (V4 path)
    constexpr int BN2 = NPAD / 16;           // float2/thread (V2 path)
    constexpr int GBUF = 64 * GSTR * 4;      // 5120
    constexpr int OFF_B = 2 * GBUF;          // 10240
    constexpr int BBUF = 32 * SBH * 2;

    extern __shared__ char smem[];
    const uint32_t sb32 = smem_u32(smem);
    const int tid = threadIdx.x, wid = tid >> 5, lane = tid & 31;
    const int wr = wid >> 1, wc = wid & 1;

    const int pstart = bid * chunk;
    const int pend = min(pstart + chunk, numP);
    if (pstart >= numP) return;
    const int nsteps = (pend - pstart + 31) >> 5;

    float4 gpre[2];
    float4 bpre4[V4 ? BN4 : 1];
    float2 bpre2[V4 ? 1 : BN2];

    auto ldg_step = [&](int pt) {
        // G: 64 rows x 32 p = 512 float4; 2 per thread
#pragma unroll
        for (int j = 0; j < 2; j++) {
            int idx = tid + j * 256;
            int b = idx >> 3, q = idx & 7, p = pt + 4 * q;
            gpre[j] = (p < pend) ? *(const float4*)&G[(size_t)b * TOTP + pbase + p]
                                 : make_float4(0.f, 0.f, 0.f, 0.f);
        }
        if constexpr (V4) {
#pragma unroll
            for (int j = 0; j < BN4; j++) {
                int idx = tid + j * 256;
                int k = idx / (NPAD / 4), c4 = idx % (NPAD / 4), c = 4 * c4, p = pt + k;
                bpre4[j] = (p < pend && c < KG) ? *(const float4*)&Bm[(size_t)p * KG + c]
                                                : make_float4(0.f, 0.f, 0.f, 0.f);
            }
        } else {
#pragma unroll
            for (int j = 0; j < BN2; j++) {
                int idx = tid + j * 256;
                int k = idx / NH, h = idx % NH, c = 2 * h, p = pt + k;
                bpre2[j] = (p < pend && c < KG) ? *(const float2*)&Bm[(size_t)p * KG + c]
                                                : make_float2(0.f, 0.f);
            }
        }
    };
    auto sts_step = [&](int buf, int pt) {
        char* gb = smem + buf * GBUF;
        char* bb = smem + OFF_B + buf * BBUF;
#pragma unroll
        for (int j = 0; j < 2; j++) {
            int idx = tid + j * 256;
            int b = idx >> 3, q = idx & 7;
            uint2 v;
            v.x = cvt_h16(gpre[j].x, gpre[j].y);
            v.y = cvt_h16(gpre[j].z, gpre[j].w);
            *(uint2*)(gb + (b * GSTR + 2 * q) * 4) = v;
        }
        if constexpr (V4) {
#pragma unroll
            for (int j = 0; j < BN4; j++) {
                int idx = tid + j * 256;
                int k = idx / (NPAD / 4), c4 = idx % (NPAD / 4), c = 4 * c4, p = pt + k;
                uint2 v;
                v.x = cvt_h16(bpre4[j].x, bpre4[j].y);
                v.y = cvt_h16(bpre4[j].z, bpre4[j].w);
                *(uint2*)(bb + (k * (SBH / 2) + 2 * c4) * 4) = v;
                if (p < pend && c < KGP2)
                    *(uint2*)(BmH + (size_t)p * KGP2 + c) = v;
            }
        } else {
#pragma unroll
            for (int j = 0; j < BN2; j++) {
                int idx = tid + j * 256;
                int k = idx / NH, h = idx % NH, c = 2 * h, p = pt + k;
                uint32_t v16 = cvt_h16(bpre2[j].x, bpre2[j].y);
                ((uint32_t*)bb)[k * (SBH / 2) + h] = v16;
                if (p < pend && c < KGP2)
                    *(uint32_t*)(BmH + (size_t)p * KGP2 + c) = v16;
            }
        }
    };

    float acc[NT][4];
#pragma unroll
    for (int t = 0; t < NT; t++)
#pragma unroll
        for (int i = 0; i < 4; i++) acc[t][i] = 0.0f;

    ldg_step(pstart);
    sts_step(0, pstart);
    __syncthreads();

    for (int s = 0; s < nsteps; s++) {
        const int cur = s & 1;
        if (s + 1 < nsteps) ldg_step(pstart + (s + 1) * 32);
        const uint32_t gB = sb32 + cur * GBUF;
        const uint32_t bB = sb32 + OFF_B + cur * BBUF;
#pragma unroll
        for (int kk = 0; kk < 2; kk++) {
            uint32_t ah[4];
            uint32_t ra = (uint32_t)((wr * 16 + (lane & 15)) * 80 + kk * 32 + (lane >> 4) * 16);
            LDSM_X4(ah, gB + ra);
            uint32_t rb = (uint32_t)((kk * 16 + (lane & 15)) * (SBH * 2));
#pragma unroll
            for (int g = 0; g < NG; g++) {
                uint32_t cb = (uint32_t)((wc * NH + g * 16 + (lane >> 4) * 8) * 2);
                uint32_t bh[4];
                LDSM_X4T(bh, bB + rb + cb);
                MMA16816(acc[2 * g],     ah, bh[0], bh[1]);
                MMA16816(acc[2 * g + 1], ah, bh[2], bh[3]);
            }
        }
        if (s + 1 < nsteps) sts_step(cur ^ 1, pstart + (s + 1) * 32);
        __syncthreads();
    }

    const int m0 = wr * 16 + (lane >> 2);
#pragma unroll
    for (int t = 0; t < NT; t++) {
        int n0 = wc * NH + t * 8 + (lane & 3) * 2;
        if (n0 < KG) {
            atomicAdd(&g_E[m0 * KTOT + koff + n0], acc[t][0]);
            atomicAdd(&g_E[(m0 + 8) * KTOT + koff + n0], acc[t][2]);
        }
        if (n0 + 1 < KG) {
            atomicAdd(&g_E[m0 * KTOT + koff + n0 + 1], acc[t][1]);
            atomicAdd(&g_E[(m0 + 8) * KTOT + koff + n0 + 1], acc[t][3]);
        }
    }
}

__global__ __launch_bounds__(256, 2) void k_gemm1_all(
    const float* __restrict__ G, const float* __restrict__ B0,
    const float* __restrict__ B1, const float* __restrict__ B2)
{
    const int bx = blockIdx.x;
    if (bx < 48)       gemm1_body<104,128,104,true >(G, B0, g_BmH,            100000,      0,   0, 2112, bx);
    else if (bx < 194) gemm1_body<156,160,160,true >(G, B1, g_BmH + BMH_OFF1, 225000, 100000, 104, 1568, bx - 48);
    else               gemm1_body<138,160,144,false>(G, B2, g_BmH + BMH_OFF2, 175000, 325000, 260, 1728, bx - 194);
}

// =============== GEMM2 (transposed): D[b][p] = sum_k E[b][k]*Bm[p][k] =====================
// A = E (register fragments, loaded once); B = Bm fp16 via cp.async ring of 8.
// Two k32 steps per wait+sync (paired); tiles of 64 p.  [R13 structure]
template <int KG, int KK, int KGP2>
__device__ void gemm2_body(const float* __restrict__ G, const __half* __restrict__ BmH,
                           float* __restrict__ out_tg, int numP, int pbase, int koff,
                           int ntiles, int cl, int NCg)
{
    constexpr int KPAD = KK * 32;
    constexpr int NK16 = 2 * KK;
    constexpr int SBH = KPAD + 8;
    constexpr int ESZ = 64 * SBH * 2;
    constexpr int OFF_RING = ESZ;
    constexpr int SSZ = 64 * 80;             // 64 rows x 80B
    constexpr int NPAIR = (KK + 1) / 2;

    extern __shared__ char smem[];
    const uint32_t sb32 = smem_u32(smem);
    const int tid = threadIdx.x, wid = tid >> 5, lane = tid & 31;
    const int wr = wid >> 1, wc = wid & 1;

    // stage E (single fp16)
    for (int idx = tid; idx < 64 * (KPAD / 2); idx += 256) {
        int b = idx / (KPAD / 2), h = idx % (KPAD / 2), k = 2 * h;
        float2 v = make_float2(0.f, 0.f);
        if (k < KG) v = *(const float2*)&g_E[b * KTOT + koff + k];
        ((uint32_t*)smem)[b * (SBH / 2) + h] = cvt_h16(v.x, v.y);
    }
    __syncthreads();

    // load E fragments once
    uint32_t ef[NK16][4];
#pragma unroll
    for (int j = 0; j < NK16; j++) {
        uint32_t ra = (uint32_t)((wr * 16 + (lane & 15)) * (SBH * 2) + j * 32 + (lane >> 4) * 16);
        LDSM_X4(ef[j], sb32 + ra);
    }

    const int myT = (cl < ntiles) ? ((ntiles - cl + NCg - 1) / NCg) : 0;
    const int total = myT * KK;

    const int r_cp = tid >> 2, ch_cp = tid & 3;
    auto issue = [&](int gs) {
        if (gs >= total) return;
        const int tj = gs / KK, st = gs - tj * KK;
        const int p0 = (cl + tj * NCg) * 64;
        const int kb = st * 64 + ch_cp * 16;
        const int p = p0 + r_cp;
        int rem = (p < numP) ? (KG * 2 - kb) : 0;
        int bytes = rem <= 0 ? 0 : (rem >= 16 ? 16 : rem);
        const char* src = (const char*)BmH + (bytes > 0 ? ((size_t)p * KGP2 * 2 + kb) : 0);
        cp_async16(sb32 + OFF_RING + (gs & 7) * SSZ + r_cp * 80 + ch_cp * 16, src, bytes);
    };

    const int bA = wr * 16 + (lane >> 2), bB = bA + 8;
    const int pofs = wc * 32 + (lane & 3) * 2;
    float gpre[16];
    float acc[4][4];
    float rsA = 0.f, rsB = 0.f;
#pragma unroll
    for (int t = 0; t < 4; t++)
#pragma unroll
        for (int i = 0; i < 4; i++) acc[t][i] = 0.0f;

#pragma unroll
    for (int i = 0; i < 6; i++) { issue(i); cp_commit(); }

    int gsb = 0;
    for (int tile = cl; tile < ntiles; tile += NCg) {
        const int p0 = tile * 64;
#pragma unroll
        for (int t = 0; t < 4; t++) {
            int p = p0 + pofs + t * 8;
            bool v = p < numP;
            float2 a = v ? *(const float2*)&G[(size_t)bA * TOTP + pbase + p] : make_float2(0.f, 0.f);
            float2 b = v ? *(const float2*)&G[(size_t)bB * TOTP + pbase + p] : make_float2(0.f, 0.f);
            gpre[4 * t + 0] = a.x; gpre[4 * t + 1] = a.y;
            gpre[4 * t + 2] = b.x; gpre[4 * t + 3] = b.y;
        }

#pragma unroll
        for (int sp = 0; sp < NPAIR; sp++) {
            const bool full = (sp * 2 + 1 < KK);
            if (full) cp_waitg<4>(); else cp_waitg<5>();
            __syncthreads();
#pragma unroll
            for (int u = 0; u < 2; u++) {
                const int st = sp * 2 + u;
                if (st >= KK) break;
                const int gs = gsb + st;
                const uint32_t aB = sb32 + OFF_RING + (gs & 7) * SSZ;
#pragma unroll
                for (int kk2 = 0; kk2 < 2; kk2++) {
                    const int j = st * 2 + kk2;
#pragma unroll
                    for (int g = 0; g < 2; g++) {
                        uint32_t rb = (uint32_t)((wc * 32 + g * 16 + (lane & 15)) * 80 + kk2 * 32 + (lane >> 4) * 16);
                        uint32_t bh[4];
                        LDSM_X4(bh, aB + rb);
                        MMA16816(acc[2 * g],     ef[j], bh[0], bh[2]);
                        MMA16816(acc[2 * g + 1], ef[j], bh[1], bh[3]);
                    }
                }
            }
            {
                const int gs = gsb + sp * 2;
                issue(gs + 6); cp_commit();
                if (full) { issue(gs + 7); cp_commit(); }
            }
        }
        gsb += KK;

        // epilogue
        float cs[8];
#pragma unroll
        for (int t = 0; t < 4; t++) {
            const int p = p0 + pofs + t * 8;
            const bool v = p < numP;
            const size_t gp = (size_t)(pbase + p);
            float gA0 = gpre[4 * t + 0], gA1 = gpre[4 * t + 1];
            float gB0 = gpre[4 * t + 2], gB1 = gpre[4 * t + 3];
            float rA0 = gA0 - acc[t][0], rA1 = gA1 - acc[t][1];
            float rB0 = gB0 - acc[t][2], rB1 = gB1 - acc[t][3];
            if (v) {
                __half2 hA = __floats2half2_rn(rA0, rA1);
                __half2 hB = __floats2half2_rn(rB0, rB1);
                *(uint32_t*)(g_residH + (size_t)bA * TOTP + gp) = *(uint32_t*)&hA;
                *(uint32_t*)(g_residH + (size_t)bB * TOTP + gp) = *(uint32_t*)&hB;
            }
            rsA += rA0 * rA0 + rA1 * rA1;
            rsB += rB0 * rB0 + rB1 * rB1;
            cs[2 * t]     = gA0 + gB0;
            cs[2 * t + 1] = gA1 + gB1;
#pragma unroll
            for (int i = 0; i < 4; i++) acc[t][i] = 0.0f;
        }
#pragma unroll
        for (int q = 0; q < 8; q++) {
            float v = cs[q];
            v += __shfl_xor_sync(~0u, v, 4);
            v += __shfl_xor_sync(~0u, v, 8);
            v += __shfl_xor_sync(~0u, v, 16);
            cs[q] = v;
        }
        if (lane < 4) {
#pragma unroll
            for (int t = 0; t < 4; t++) {
                int p = p0 + wc * 32 + t * 8 + lane * 2;
                if (p < numP)     atomicAdd(&out_tg[p],     cs[2 * t]     * (1.0f / BATCH));
                if (p + 1 < numP) atomicAdd(&out_tg[p + 1], cs[2 * t + 1] * (1.0f / BATCH));
            }
        }
    }
    cp_waitg<0>();

    rsA += __shfl_xor_sync(~0u, rsA, 1); rsA += __shfl_xor_sync(~0u, rsA, 2);
    rsB += __shfl_xor_sync(~0u, rsB, 1); rsB += __shfl_xor_sync(~0u, rsB, 2);
    if ((lane & 3) == 0) {
        atomicAdd(&g_rsq[bA], rsA);
        atomicAdd(&g_rsq[bB], rsB);
    }
}

__global__ __launch_bounds__(256, 2) void k_gemm2_all(
    const float* __restrict__ G, float* __restrict__ out_tg)
{
    const int bx = blockIdx.x;
    if (bx < 49)       gemm2_body<104,4,104>(G, g_BmH,            out_tg,          100000,      0,   0, 1563, bx,        49);
    else if (bx < 188) gemm2_body<156,5,160>(G, g_BmH + BMH_OFF1, out_tg + 100000, 225000, 100000, 104, 3516, bx - 49,  139);
    else               gemm2_body<138,5,144>(G, g_BmH + BMH_OFF2, out_tg + 325000, 175000, 325000, 260, 2735, bx - 188, 108);
}

// ---------------- launch ----------------
extern "C" void kernel_launch(void* const* d_in, const int* in_sizes, int n_in,
                              void* d_out, int out_size) {
    (void)in_sizes; (void)n_in; (void)out_size;
    const float* G  = (const float*)d_in[0];
    const float* B0 = (const float*)d_in[1];
    const float* B1 = (const float*)d_in[2];
    const float* B2 = (const float*)d_in[3];
    float* out = (float*)d_out;
    float* out_tg = out + 398 + TOTP;

    static bool attr_done = false;
    if (!attr_done) {
        cudaFuncSetAttribute(k_gemm2_all, cudaFuncAttributeMaxDynamicSharedMemorySize, 62464);
        attr_done = true;
    }

    k_init<<<256, 256>>>(out_tg);

    // gemm1: persistent single wave, 128-bit staging
    k_gemm1_all<<<296, 256, 31744>>>(G, B0, B1, B2);

    k_embed<<<1, 256>>>(out);

    // gemm2 smem: ESZ(max 21504) + 8*5120 = 62464
    k_gemm2_all<<<296, 256, 62464>>>(G, out_tg);

    k_final<<<(TOTP / 8 + 255) / 256, 256>>>(out + 398);
}